// round 15
// baseline (speedup 1.0000x reference)
#include <cuda_runtime.h>
#include <cuda_fp16.h>
#include <cstdint>

// ---------------------------------------------------------------------------
// Problem dims
// ---------------------------------------------------------------------------
#define Bdim 4
#define Tdim 2048
#define Cdim 1024
#define Hdim 16
#define Rdim 256
#define Sdim 64
#define Ddim 64
#define Mrows (Bdim * Tdim)   // 8192
#define ATTN_SCALE 0.125f     // 1/sqrt(64)

// Scratch (device globals; no allocation allowed)
__device__ __align__(16) __half g_qh[Bdim * Hdim * Tdim * Sdim];
__device__ __align__(16) __half g_kh[Bdim * Hdim * Tdim * Sdim];
__device__ __align__(16) __half g_vh[Bdim * Hdim * Tdim * Ddim];
__device__ __align__(16) __half g_xh[Mrows * Cdim];
__device__ __align__(16) __half g_bwh[Rdim * Cdim];
__device__ __align__(16) __half g_vwh[Cdim * Cdim];
__device__ __align__(16) __half g_owh[Cdim * Cdim];
__device__ __align__(16) __half g_wh[Hdim * 128 * 256];    // [H][128][256]=[Uh^T;Vh^T]
__device__ __align__(16) __half g_lath[Mrows * Rdim];
__device__ __align__(16) __half g_yh[Mrows * Cdim];

// ---------------------------------------------------------------------------
// helpers
// ---------------------------------------------------------------------------
__device__ __forceinline__ void mma_f16(float& d0, float& d1, float& d2, float& d3,
                                        uint32_t a0, uint32_t a1, uint32_t a2, uint32_t a3,
                                        uint32_t b0, uint32_t b1)
{
    asm volatile(
        "mma.sync.aligned.m16n8k16.row.col.f32.f16.f16.f32 "
        "{%0,%1,%2,%3}, {%4,%5,%6,%7}, {%8,%9}, {%0,%1,%2,%3};"
        : "+f"(d0), "+f"(d1), "+f"(d2), "+f"(d3)
        : "r"(a0), "r"(a1), "r"(a2), "r"(a3), "r"(b0), "r"(b1));
}

__device__ __forceinline__ void ldmatrix_x4(
    uint32_t& r0, uint32_t& r1, uint32_t& r2, uint32_t& r3, uint32_t saddr)
{
    asm volatile(
        "ldmatrix.sync.aligned.m8n8.x4.shared.b16 {%0,%1,%2,%3}, [%4];"
        : "=r"(r0), "=r"(r1), "=r"(r2), "=r"(r3)
        : "r"(saddr));
}

__device__ __forceinline__ void ldmatrix_x4_trans(
    uint32_t& r0, uint32_t& r1, uint32_t& r2, uint32_t& r3, uint32_t saddr)
{
    asm volatile(
        "ldmatrix.sync.aligned.m8n8.x4.trans.shared.b16 {%0,%1,%2,%3}, [%4];"
        : "=r"(r0), "=r"(r1), "=r"(r2), "=r"(r3)
        : "r"(saddr));
}

__device__ __forceinline__ void cp16(void* dst_smem, const void* src) {
    uint32_t s = (uint32_t)__cvta_generic_to_shared(dst_smem);
    asm volatile("cp.async.ca.shared.global [%0], [%1], 16;" :: "r"(s), "l"(src));
}
#define CP_COMMIT() asm volatile("cp.async.commit_group;")
#define CP_WAIT0()  asm volatile("cp.async.wait_group 0;")
#define CP_WAIT1()  asm volatile("cp.async.wait_group 1;")

// FFMA-only exp (avoids MUFU bottleneck). Valid for x <= 0 (clamped at -87).
__device__ __forceinline__ float fexp(float x) {
    x = fmaxf(x, -87.0f);
    float t = fmaf(x, 1.4426950408889634f, 12582912.f);
    int   ib = __float_as_int(t);
    float i  = t - 12582912.f;
    float f  = fmaf(x, 1.4426950408889634f, -i);
    float p  = fmaf(f, 0.00133336f, 0.0096181f);
    p = fmaf(f, p, 0.0555041f);
    p = fmaf(f, p, 0.2402265f);
    p = fmaf(f, p, 0.6931472f);
    p = fmaf(f, p, 1.0f);
    float sc = __int_as_float((ib << 23) + 0x3F800000);
    return sc * p;
}

__device__ __forceinline__ uint32_t packh2(float a, float b) {
    __half2 h = __floats2half2_rn(a, b);
    return *(uint32_t*)&h;
}

// ---------------------------------------------------------------------------
// one-shot prep: all fp32->fp16 conversions in a single launch
// ---------------------------------------------------------------------------
#define NX4 (Mrows * Cdim / 4)
#define NB4 (Rdim * Cdim / 4)
#define NV4 (Cdim * Cdim / 4)
#define NCVT (NX4 + NB4 + 2 * NV4)

__global__ void cvt_all(const float* __restrict__ x, const float* __restrict__ bw,
                        const float* __restrict__ vw, const float* __restrict__ ow,
                        __half* __restrict__ xh, __half* __restrict__ bwh,
                        __half* __restrict__ vwh, __half* __restrict__ owh)
{
    int i = blockIdx.x * 256 + threadIdx.x;
    const float* src; __half* dst; int j;
    if (i < NX4)                  { src = x;  dst = xh;  j = i; }
    else if (i < NX4 + NB4)       { src = bw; dst = bwh; j = i - NX4; }
    else if (i < NX4 + NB4 + NV4) { src = vw; dst = vwh; j = i - NX4 - NB4; }
    else if (i < NCVT)            { src = ow; dst = owh; j = i - NX4 - NB4 - NV4; }
    else return;
    float4 v = ((const float4*)src)[j];
    ((__half2*)dst)[2 * j]     = __floats2half2_rn(v.x, v.y);
    ((__half2*)dst)[2 * j + 1] = __floats2half2_rn(v.z, v.w);
}

__global__ void build_w(const float* __restrict__ u, const float* __restrict__ v,
                        __half* __restrict__ w)
{
    int idx = blockIdx.x * 256 + threadIdx.x;
    if (idx >= Hdim * 128 * 256) return;
    int r = idx & 255;
    int n = (idx >> 8) & 127;
    int h = idx >> 15;
    float val = (n < 64)
        ? u[((size_t)h * Rdim + r) * Sdim + n]
        : v[((size_t)h * Rdim + r) * Sdim + (n - 64)];
    w[idx] = __float2half_rn(val);
}

// ---------------------------------------------------------------------------
// fp16 mma.sync NT GEMM body (unchanged round-13/14 config)
// ---------------------------------------------------------------------------
#define HP 72   // smem pitch in halfs
template <int LAYOUT, bool HAS_BIAS, int OUT>
__device__ __forceinline__ void gemm_body(
    const __half* __restrict__ A, const __half* __restrict__ Bw,
    const float* __restrict__ bias, void* __restrict__ Cv,
    void* __restrict__ C2v, int Ndim_, int Kdim_, int bm, int bn, int head)
{
    extern __shared__ __half smh[];
    __half* As = smh;                   // [3][128][72]
    __half* Bs = smh + 3 * 128 * HP;    // [3][128][72]

    const int tid = threadIdx.x;
    const int lane = tid & 31;
    const int warp = tid >> 5;
    const int wy = warp & 1;
    const int wx = warp >> 1;

    if (LAYOUT == 2) Bw += (size_t)head * (128 * 256);

    const int sr = tid >> 3;
    const int sc8 = (tid & 7) * 8;

    const __half* Abase = A + (size_t)bm * Kdim_;
    const __half* Bbase = Bw + (size_t)bn * Kdim_;

    float acc[4][4][4];
#pragma unroll
    for (int i = 0; i < 4; i++)
#pragma unroll
        for (int j = 0; j < 4; j++)
#pragma unroll
            for (int e = 0; e < 4; e++) acc[i][j][e] = 0.f;

    const int nch = Kdim_ >> 6;

    auto load_chunk = [&](int ch, int buf) {
        const __half* An = Abase + ch * 64;
        const __half* Bn = Bbase + ch * 64;
        __half* Ad = As + buf * 128 * HP;
        __half* Bd = Bs + buf * 128 * HP;
#pragma unroll
        for (int i = 0; i < 4; i++) {
            int r = sr + i * 32;
            cp16(Ad + r * HP + sc8, An + (size_t)r * Kdim_ + sc8);
            cp16(Bd + r * HP + sc8, Bn + (size_t)r * Kdim_ + sc8);
        }
        CP_COMMIT();
    };

    load_chunk(0, 0);
    if (nch > 1) load_chunk(1, 1);

    const int quad = lane >> 3;
    const int r8 = lane & 7;
    const int a_off = ((quad & 1) * 8 + r8) * HP + (quad >> 1) * 8;
    const int b_off = ((quad >> 1) * 8 + r8) * HP + (quad & 1) * 8;

    const uint32_t smem_s = (uint32_t)__cvta_generic_to_shared(smh);
    const uint32_t asl = smem_s + (wy * 64 * HP + a_off) * 2;
    const uint32_t bsl = smem_s + (3 * 128 * HP + wx * 32 * HP + b_off) * 2;

    int buf = 0;
    for (int ch = 0; ch < nch; ch++) {
        if (ch + 1 < nch) { CP_WAIT1(); } else { CP_WAIT0(); }
        __syncthreads();

        if (ch + 2 < nch) {
            int nb = buf + 2; if (nb >= 3) nb -= 3;
            load_chunk(ch + 2, nb);
        }

        const uint32_t ab = asl + (buf * 128 * HP) * 2;
        const uint32_t bb = bsl + (buf * 128 * HP) * 2;
#pragma unroll
        for (int ks = 0; ks < 4; ks++) {
            const int kk2 = ks * 16 * 2;
            uint32_t af[4][4];
#pragma unroll
            for (int mf = 0; mf < 4; mf++)
                ldmatrix_x4(af[mf][0], af[mf][1], af[mf][2], af[mf][3],
                            ab + (mf * 16 * HP) * 2 + kk2);
            uint32_t bf[4][2];
#pragma unroll
            for (int p = 0; p < 2; p++)
                ldmatrix_x4(bf[2 * p][0], bf[2 * p][1], bf[2 * p + 1][0], bf[2 * p + 1][1],
                            bb + (p * 16 * HP) * 2 + kk2);
#pragma unroll
            for (int mf = 0; mf < 4; mf++)
#pragma unroll
                for (int nf = 0; nf < 4; nf++)
                    mma_f16(acc[mf][nf][0], acc[mf][nf][1], acc[mf][nf][2], acc[mf][nf][3],
                            af[mf][0], af[mf][1], af[mf][2], af[mf][3],
                            bf[nf][0], bf[nf][1]);
        }
        if (++buf == 3) buf = 0;
    }

    const int g = lane >> 2;
    const int tg = lane & 3;
#pragma unroll
    for (int mf = 0; mf < 4; mf++) {
#pragma unroll
        for (int nf = 0; nf < 4; nf++) {
            const int m0 = bm + wy * 64 + mf * 16 + g;
            const int n0 = bn + wx * 32 + nf * 8 + tg * 2;
            float v0 = acc[mf][nf][0], v1 = acc[mf][nf][1];
            float v2 = acc[mf][nf][2], v3 = acc[mf][nf][3];
            if (HAS_BIAS) {
                float b0 = bias[n0], b1 = bias[n0 + 1];
                v0 += b0; v1 += b1; v2 += b0; v3 += b1;
            }
            if (LAYOUT == 2 && n0 < 64) {
                v0 *= ATTN_SCALE; v1 *= ATTN_SCALE; v2 *= ATTN_SCALE; v3 *= ATTN_SCALE;
            }

            if (OUT == 2) {
                __half2 lo = __floats2half2_rn(v0, v1);
                __half2 hi = __floats2half2_rn(v2, v3);
                if (LAYOUT == 0) {
                    __half* C = (__half*)Cv;
                    *(__half2*)(C + (size_t)m0 * Ndim_ + n0) = lo;
                    *(__half2*)(C + (size_t)(m0 + 8) * Ndim_ + n0) = hi;
                } else if (LAYOUT == 1) {
                    __half* C = (__half*)Cv;
                    const int h = n0 >> 6, d = n0 & 63;
                    const int b_ = m0 >> 11, t = m0 & 2047;
                    __half* dst = C + (((size_t)b_ * Hdim + h) * Tdim + t) * Ddim + d;
                    *(__half2*)dst = lo;
                    *(__half2*)(dst + 8 * Ddim) = hi;
                } else {
                    __half* base = (n0 < 64) ? (__half*)Cv : (__half*)C2v;
                    const int s0 = n0 & 63;
                    const int b_ = m0 >> 11, t = m0 & 2047;
                    __half* dst = base + (((size_t)b_ * Hdim + head) * Tdim + t) * Sdim + s0;
                    *(__half2*)dst = lo;
                    *(__half2*)(dst + 8 * Sdim) = hi;
                }
            } else {
                float* C = (float*)Cv;
                *(float2*)(C + (size_t)m0 * Ndim_ + n0) = make_float2(v0, v1);
                *(float2*)(C + (size_t)(m0 + 8) * Ndim_ + n0) = make_float2(v2, v3);
            }
        }
    }
}

template <int LAYOUT, bool HAS_BIAS, int OUT>
__global__ void __launch_bounds__(256, 2)
gemm_h(const __half* __restrict__ A, const __half* __restrict__ Bw,
       const float* __restrict__ bias, void* __restrict__ Cv,
       void* __restrict__ C2v, int Ndim_, int Kdim_)
{
    gemm_body<LAYOUT, HAS_BIAS, OUT>(A, Bw, bias, Cv, C2v, Ndim_, Kdim_,
                                     blockIdx.y * 128, blockIdx.x * 128, blockIdx.z);
}

// Merged latent + v-proj kernel: flat grid of 128 (latent) + 512 (v) CTAs.
__global__ void __launch_bounds__(256, 2)
gemm_lv(const __half* __restrict__ xh, const __half* __restrict__ bwh,
        const __half* __restrict__ vwh, const float* __restrict__ vb,
        __half* __restrict__ lat, __half* __restrict__ vh)
{
    const int c = blockIdx.x;
    if (c < 128) {
        gemm_body<0, false, 2>(xh, bwh, nullptr, lat, nullptr, Rdim, Cdim,
                               (c >> 1) * 128, (c & 1) * 128, 0);
    } else {
        const int c2 = c - 128;
        gemm_body<1, true, 2>(xh, vwh, vb, vh, nullptr, Cdim, Cdim,
                              (c2 >> 3) * 128, (c2 & 7) * 128, 0);
    }
}

// ---------------------------------------------------------------------------
// Flash attention, fp16 mma.sync, fp32 accum.
// Q tile 256 rows; 8 warps, each owns 32 rows (2 m16 blocks) -> every K/V
// B-fragment load feeds 2x mma work (K/V smem reads per unit work ~halved).
// Q fragments hoisted to registers. 3-stage cp.async K/V. 1 CTA/SM.
// ---------------------------------------------------------------------------
__global__ void __launch_bounds__(256, 1)
flash_h(const __half* __restrict__ q, const __half* __restrict__ k,
        const __half* __restrict__ v, __half* __restrict__ y)
{
    extern __shared__ __half fsh[];
    __half* Qs = fsh;                  // [256][72] (staging only)
    __half* Ks = Qs + 256 * HP;        // [3][64][72]
    __half* Vs = Ks + 3 * 64 * HP;     // [3][64][72] natural [u][d]

    const int bh = blockIdx.y;
    const int b = bh >> 4, h = bh & 15;
    const int qb = (gridDim.x - 1) - blockIdx.x;   // heaviest tiles first
    const int q0 = qb * 256;
    const __half* Q = q + (size_t)bh * Tdim * Sdim;
    const __half* K = k + (size_t)bh * Tdim * Sdim;
    const __half* V = v + (size_t)bh * Tdim * Ddim;

    const int tid = threadIdx.x;
    const int lane = tid & 31;
    const int warp = tid >> 5;
    const int wrow = warp * 32;        // 32 q-rows per warp
    const int g = lane >> 2;
    const int tg = lane & 3;

    const int nkt = (q0 + 256) >> 6;   // >= 4

    auto load_kv = [&](int kt, int st) {
        const int k0 = kt * 64;
        __half* Kd = Ks + st * 64 * HP;
        __half* Vd = Vs + st * 64 * HP;
#pragma unroll
        for (int i = 0; i < 2; i++) {
            int f = tid + i * 256;
            int u = f >> 3, c8 = (f & 7) * 8;
            cp16(Kd + u * HP + c8, K + (size_t)(k0 + u) * Sdim + c8);
            cp16(Vd + u * HP + c8, V + (size_t)(k0 + u) * Ddim + c8);
        }
        CP_COMMIT();
    };

    load_kv(0, 0);
    load_kv(1, 1);

    // stage Q tile: 256 rows x 64 halfs = 2048 uint4 -> 8 per thread
#pragma unroll
    for (int i = 0; i < 8; i++) {
        int f = tid + i * 256;
        int r = f >> 3, c8 = (f & 7) * 8;
        *(uint4*)&Qs[r * HP + c8] = *(const uint4*)&Q[(size_t)(q0 + r) * Sdim + c8];
    }

    const unsigned FULL = 0xffffffffu;
    const int quad = lane >> 3;
    const int r8 = lane & 7;
    const int a_off = ((quad & 1) * 8 + r8) * HP + (quad >> 1) * 8;
    const int b_off = ((quad >> 1) * 8 + r8) * HP + (quad & 1) * 8;
    const int lm_row = ((lane >> 3) & 1) * 8 + (lane & 7);
    const int lm_dfo = lane >> 4;

    const uint32_t fsh_s = (uint32_t)__cvta_generic_to_shared(fsh);
    const uint32_t qa_s = fsh_s + (wrow * HP + a_off) * 2;
    const uint32_t ks_s = fsh_s + (256 * HP + b_off) * 2;

    // publish Qs, hoist Q A-fragments (2 m-blocks x 4 k-steps)
    __syncthreads();
    uint32_t qf[2][4][4];
#pragma unroll
    for (int mb = 0; mb < 2; mb++)
#pragma unroll
        for (int ks = 0; ks < 4; ks++)
            ldmatrix_x4(qf[mb][ks][0], qf[mb][ks][1], qf[mb][ks][2], qf[mb][ks][3],
                        qa_s + (mb * 16 * HP) * 2 + ks * 16 * 2);

    float o[2][8][4];
#pragma unroll
    for (int mb = 0; mb < 2; mb++)
#pragma unroll
        for (int df = 0; df < 8; df++)
#pragma unroll
            for (int e = 0; e < 4; e++) o[mb][df][e] = 0.f;
    float mrow[4] = {-1e30f, -1e30f, -1e30f, -1e30f};   // [mb*2 + half]
    float lrow[4] = {0.f, 0.f, 0.f, 0.f};

    int st = 0;
    for (int kt = 0; kt < nkt; kt++) {
        if (kt + 1 < nkt) { CP_WAIT1(); } else { CP_WAIT0(); }
        __syncthreads();

        if (kt + 2 < nkt) {
            int ns = st + 2; if (ns >= 3) ns -= 3;
            load_kv(kt + 2, ns);
        }

        const __half* Vb = Vs + st * 64 * HP;
        const uint32_t kb = ks_s + (st * 64 * HP) * 2;
        const int k0 = kt * 64;

        // S = Q K^T (per warp: 32 x 64); K B-frags shared by both m-blocks
        float sacc[2][8][4];
#pragma unroll
        for (int mb = 0; mb < 2; mb++)
#pragma unroll
            for (int jf = 0; jf < 8; jf++)
#pragma unroll
                for (int e = 0; e < 4; e++) sacc[mb][jf][e] = 0.f;
#pragma unroll
        for (int ks = 0; ks < 4; ks++) {
            const int kk2 = ks * 16 * 2;
            uint32_t bf[8][2];
#pragma unroll
            for (int p = 0; p < 4; p++)
                ldmatrix_x4(bf[2 * p][0], bf[2 * p][1], bf[2 * p + 1][0], bf[2 * p + 1][1],
                            kb + (p * 16 * HP) * 2 + kk2);
#pragma unroll
            for (int jf = 0; jf < 8; jf++) {
                mma_f16(sacc[0][jf][0], sacc[0][jf][1], sacc[0][jf][2], sacc[0][jf][3],
                        qf[0][ks][0], qf[0][ks][1], qf[0][ks][2], qf[0][ks][3],
                        bf[jf][0], bf[jf][1]);
                mma_f16(sacc[1][jf][0], sacc[1][jf][1], sacc[1][jf][2], sacc[1][jf][3],
                        qf[1][ks][0], qf[1][ks][1], qf[1][ks][2], qf[1][ks][3],
                        bf[jf][0], bf[jf][1]);
            }
        }

        // causal mask (warp covers rows q0+wrow .. +31)
        if (k0 + 63 > q0 + wrow) {
#pragma unroll
            for (int mb = 0; mb < 2; mb++) {
                const int r0 = q0 + wrow + mb * 16 + g;
                const int r1 = r0 + 8;
#pragma unroll
                for (int jf = 0; jf < 8; jf++) {
                    const int c0 = k0 + jf * 8 + 2 * tg;
                    if (c0 > r0) sacc[mb][jf][0] = -1e30f;
                    if (c0 + 1 > r0) sacc[mb][jf][1] = -1e30f;
                    if (c0 > r1) sacc[mb][jf][2] = -1e30f;
                    if (c0 + 1 > r1) sacc[mb][jf][3] = -1e30f;
                }
            }
        }

        // online softmax (4 row-groups: mb x half; reduction over tg lanes)
#pragma unroll
        for (int mb = 0; mb < 2; mb++) {
            float mx0 = -1e30f, mx1 = -1e30f;
#pragma unroll
            for (int jf = 0; jf < 8; jf++) {
                mx0 = fmaxf(mx0, fmaxf(sacc[mb][jf][0], sacc[mb][jf][1]));
                mx1 = fmaxf(mx1, fmaxf(sacc[mb][jf][2], sacc[mb][jf][3]));
            }
            mx0 = fmaxf(mx0, __shfl_xor_sync(FULL, mx0, 1));
            mx0 = fmaxf(mx0, __shfl_xor_sync(FULL, mx0, 2));
            mx1 = fmaxf(mx1, __shfl_xor_sync(FULL, mx1, 1));
            mx1 = fmaxf(mx1, __shfl_xor_sync(FULL, mx1, 2));

            float mn0 = fmaxf(mrow[2 * mb], mx0);
            float mn1 = fmaxf(mrow[2 * mb + 1], mx1);
            float al0 = fexp(mrow[2 * mb] - mn0);
            float al1 = fexp(mrow[2 * mb + 1] - mn1);
            mrow[2 * mb] = mn0; mrow[2 * mb + 1] = mn1;

            float rs0 = 0.f, rs1 = 0.f;
#pragma unroll
            for (int jf = 0; jf < 8; jf++) {
                sacc[mb][jf][0] = fexp(sacc[mb][jf][0] - mn0);
                sacc[mb][jf][1] = fexp(sacc[mb][jf][1] - mn0);
                sacc[mb][jf][2] = fexp(sacc[mb][jf][2] - mn1);
                sacc[mb][jf][3] = fexp(sacc[mb][jf][3] - mn1);
                rs0 += sacc[mb][jf][0] + sacc[mb][jf][1];
                rs1 += sacc[mb][jf][2] + sacc[mb][jf][3];
            }
            rs0 += __shfl_xor_sync(FULL, rs0, 1);
            rs0 += __shfl_xor_sync(FULL, rs0, 2);
            rs1 += __shfl_xor_sync(FULL, rs1, 1);
            rs1 += __shfl_xor_sync(FULL, rs1, 2);
            lrow[2 * mb] = lrow[2 * mb] * al0 + rs0;
            lrow[2 * mb + 1] = lrow[2 * mb + 1] * al1 + rs1;

#pragma unroll
            for (int df = 0; df < 8; df++) {
                o[mb][df][0] *= al0; o[mb][df][1] *= al0;
                o[mb][df][2] *= al1; o[mb][df][3] *= al1;
            }
        }

        // O += P V : V B-frags (ldmatrix.trans) shared by both m-blocks
        const uint32_t vb_s = (uint32_t)__cvta_generic_to_shared(Vb);
#pragma unroll
        for (int ks2 = 0; ks2 < 4; ks2++) {
            uint32_t a[2][4];
#pragma unroll
            for (int mb = 0; mb < 2; mb++) {
                a[mb][0] = packh2(sacc[mb][2 * ks2][0],     sacc[mb][2 * ks2][1]);
                a[mb][1] = packh2(sacc[mb][2 * ks2][2],     sacc[mb][2 * ks2][3]);
                a[mb][2] = packh2(sacc[mb][2 * ks2 + 1][0], sacc[mb][2 * ks2 + 1][1]);
                a[mb][3] = packh2(sacc[mb][2 * ks2 + 1][2], sacc[mb][2 * ks2 + 1][3]);
            }
            const uint32_t rowaddr = vb_s + ((16 * ks2 + lm_row) * HP) * 2;
#pragma unroll
            for (int df2 = 0; df2 < 4; df2++) {
                uint32_t b0, b1, b2, b3;
                ldmatrix_x4_trans(b0, b1, b2, b3,
                                  rowaddr + (16 * df2 + 8 * lm_dfo) * 2);
#pragma unroll
                for (int mb = 0; mb < 2; mb++) {
                    mma_f16(o[mb][2 * df2][0], o[mb][2 * df2][1],
                            o[mb][2 * df2][2], o[mb][2 * df2][3],
                            a[mb][0], a[mb][1], a[mb][2], a[mb][3], b0, b1);
                    mma_f16(o[mb][2 * df2 + 1][0], o[mb][2 * df2 + 1][1],
                            o[mb][2 * df2 + 1][2], o[mb][2 * df2 + 1][3],
                            a[mb][0], a[mb][1], a[mb][2], a[mb][3], b2, b3);
                }
            }
        }
        if (++st == 3) st = 0;
    }

    // epilogue: y[b, t, h*64 + d] as fp16
#pragma unroll
    for (int mb = 0; mb < 2; mb++) {
        const float inv0 = 1.f / lrow[2 * mb];
        const float inv1 = 1.f / lrow[2 * mb + 1];
        const int r0 = q0 + wrow + mb * 16 + g;
        __half* y0 = y + ((size_t)b * Tdim + r0) * Cdim + h * 64;
        __half* y1 = y + ((size_t)b * Tdim + r0 + 8) * Cdim + h * 64;
#pragma unroll
        for (int df = 0; df < 8; df++) {
            const int d0 = df * 8 + 2 * tg;
            *(__half2*)(y0 + d0) = __floats2half2_rn(o[mb][df][0] * inv0, o[mb][df][1] * inv0);
            *(__half2*)(y1 + d0) = __floats2half2_rn(o[mb][df][2] * inv1, o[mb][df][3] * inv1);
        }
    }
}

// ---------------------------------------------------------------------------
extern "C" void kernel_launch(void* const* d_in, const int* in_sizes, int n_in,
                              void* d_out, int out_size)
{
    const float* x  = (const float*)d_in[0];
    const float* bw = (const float*)d_in[1];
    const float* uf = (const float*)d_in[2];
    const float* vf = (const float*)d_in[3];
    const float* vw = (const float*)d_in[4];
    const float* vb = (const float*)d_in[5];
    const float* ow = (const float*)d_in[6];
    const float* ob = (const float*)d_in[7];
    float* out = (float*)d_out;

    __half *qh, *kh, *vh, *xh, *bwh, *vwh, *owh, *wh, *lath, *yh;
    cudaGetSymbolAddress((void**)&qh, g_qh);
    cudaGetSymbolAddress((void**)&kh, g_kh);
    cudaGetSymbolAddress((void**)&vh, g_vh);
    cudaGetSymbolAddress((void**)&xh, g_xh);
    cudaGetSymbolAddress((void**)&bwh, g_bwh);
    cudaGetSymbolAddress((void**)&vwh, g_vwh);
    cudaGetSymbolAddress((void**)&owh, g_owh);
    cudaGetSymbolAddress((void**)&wh, g_wh);
    cudaGetSymbolAddress((void**)&lath, g_lath);
    cudaGetSymbolAddress((void**)&yh, g_yh);

    const int GSMEM = 2 * 3 * 128 * HP * 2;             // 110592 bytes
    const int FSMEM = (256 + 3 * 64 + 3 * 64) * HP * 2; // 92160 bytes
    cudaFuncSetAttribute(gemm_lv,             cudaFuncAttributeMaxDynamicSharedMemorySize, GSMEM);
    cudaFuncSetAttribute(gemm_h<2, false, 2>, cudaFuncAttributeMaxDynamicSharedMemorySize, GSMEM);
    cudaFuncSetAttribute(gemm_h<0, true,  0>, cudaFuncAttributeMaxDynamicSharedMemorySize, GSMEM);
    cudaFuncSetAttribute(flash_h, cudaFuncAttributeMaxDynamicSharedMemorySize, FSMEM);

    // one-shot fp16 conversions (single launch) + factor transpose
    cvt_all<<<(NCVT + 255) / 256, 256>>>(x, bw, vw, ow, xh, bwh, vwh, owh);
    build_w<<<(Hdim * 128 * 256 + 255) / 256, 256>>>(uf, vf, wh);

    // latent (128 CTAs) merged with v-proj (512 CTAs)
    gemm_lv<<<640, 256, GSMEM>>>(xh, bwh, vwh, vb, lath, vh);

    // q,k per head (q pre-scaled) -> fp16 [B,H,T,64]
    gemm_h<2, false, 2><<<dim3(1, Mrows / 128, Hdim), 256, GSMEM>>>(
        lath, wh, nullptr, qh, kh, 128, Rdim);

    // causal flash attention (fp16 tensor cores, Q tile 256) -> y fp16
    flash_h<<<dim3(Tdim / 256, Bdim * Hdim), 256, FSMEM>>>(qh, kh, vh, yh);

    // out = y * o_proj_w^T + b (fp32 output)
    gemm_h<0, true, 0><<<dim3(Cdim / 128, Mrows / 128), 256, GSMEM>>>(
        yh, owh, ob, out, nullptr, Cdim, Cdim);
}

// round 17
// speedup vs baseline: 1.1108x; 1.1108x over previous
#include <cuda_runtime.h>
#include <cuda_fp16.h>
#include <cstdint>

// ---------------------------------------------------------------------------
// Problem dims
// ---------------------------------------------------------------------------
#define Bdim 4
#define Tdim 2048
#define Cdim 1024
#define Hdim 16
#define Rdim 256
#define Sdim 64
#define Ddim 64
#define Mrows (Bdim * Tdim)   // 8192
#define ATTN_SCALE 0.125f     // 1/sqrt(64)

// Scratch (device globals; no allocation allowed)
__device__ __align__(16) __half g_qh[Bdim * Hdim * Tdim * Sdim];
__device__ __align__(16) __half g_kh[Bdim * Hdim * Tdim * Sdim];
__device__ __align__(16) __half g_vh[Bdim * Hdim * Tdim * Ddim];
__device__ __align__(16) __half g_xh[Mrows * Cdim];
__device__ __align__(16) __half g_bwh[Rdim * Cdim];
__device__ __align__(16) __half g_vwh[Cdim * Cdim];
__device__ __align__(16) __half g_owh[Cdim * Cdim];
__device__ __align__(16) __half g_wh[Hdim * 128 * 256];    // [H][128][256]=[Uh^T;Vh^T]
__device__ __align__(16) __half g_lath[Mrows * Rdim];
__device__ __align__(16) __half g_yh[Mrows * Cdim];
__device__ int g_sync[64];   // per (batch, 128-row block) flash-completion counters

// ---------------------------------------------------------------------------
// helpers
// ---------------------------------------------------------------------------
__device__ __forceinline__ void mma_f16(float& d0, float& d1, float& d2, float& d3,
                                        uint32_t a0, uint32_t a1, uint32_t a2, uint32_t a3,
                                        uint32_t b0, uint32_t b1)
{
    asm volatile(
        "mma.sync.aligned.m16n8k16.row.col.f32.f16.f16.f32 "
        "{%0,%1,%2,%3}, {%4,%5,%6,%7}, {%8,%9}, {%0,%1,%2,%3};"
        : "+f"(d0), "+f"(d1), "+f"(d2), "+f"(d3)
        : "r"(a0), "r"(a1), "r"(a2), "r"(a3), "r"(b0), "r"(b1));
}

__device__ __forceinline__ void ldmatrix_x4(
    uint32_t& r0, uint32_t& r1, uint32_t& r2, uint32_t& r3, uint32_t saddr)
{
    asm volatile(
        "ldmatrix.sync.aligned.m8n8.x4.shared.b16 {%0,%1,%2,%3}, [%4];"
        : "=r"(r0), "=r"(r1), "=r"(r2), "=r"(r3)
        : "r"(saddr));
}

__device__ __forceinline__ void ldmatrix_x4_trans(
    uint32_t& r0, uint32_t& r1, uint32_t& r2, uint32_t& r3, uint32_t saddr)
{
    asm volatile(
        "ldmatrix.sync.aligned.m8n8.x4.trans.shared.b16 {%0,%1,%2,%3}, [%4];"
        : "=r"(r0), "=r"(r1), "=r"(r2), "=r"(r3)
        : "r"(saddr));
}

__device__ __forceinline__ void cp16(void* dst_smem, const void* src) {
    uint32_t s = (uint32_t)__cvta_generic_to_shared(dst_smem);
    asm volatile("cp.async.ca.shared.global [%0], [%1], 16;" :: "r"(s), "l"(src));
}
#define CP_COMMIT() asm volatile("cp.async.commit_group;")
#define CP_WAIT0()  asm volatile("cp.async.wait_group 0;")
#define CP_WAIT1()  asm volatile("cp.async.wait_group 1;")

// FFMA-only exp (avoids MUFU bottleneck). Valid for x <= 0 (clamped at -87).
__device__ __forceinline__ float fexp(float x) {
    x = fmaxf(x, -87.0f);
    float t = fmaf(x, 1.4426950408889634f, 12582912.f);
    int   ib = __float_as_int(t);
    float i  = t - 12582912.f;
    float f  = fmaf(x, 1.4426950408889634f, -i);
    float p  = fmaf(f, 0.00133336f, 0.0096181f);
    p = fmaf(f, p, 0.0555041f);
    p = fmaf(f, p, 0.2402265f);
    p = fmaf(f, p, 0.6931472f);
    p = fmaf(f, p, 1.0f);
    float sc = __int_as_float((ib << 23) + 0x3F800000);
    return sc * p;
}

__device__ __forceinline__ uint32_t packh2(float a, float b) {
    __half2 h = __floats2half2_rn(a, b);
    return *(uint32_t*)&h;
}

// ---------------------------------------------------------------------------
// one-shot prep: all fp32->fp16 conversions + factor transpose + sync reset
// ---------------------------------------------------------------------------
#define NX4 (Mrows * Cdim / 4)
#define NB4 (Rdim * Cdim / 4)
#define NV4 (Cdim * Cdim / 4)
#define NCVT (NX4 + NB4 + 2 * NV4)
#define NWEL (Hdim * 128 * 256)
#define NTOT (NCVT + NWEL)

__global__ void cvt_all(const float* __restrict__ x, const float* __restrict__ bw,
                        const float* __restrict__ vw, const float* __restrict__ ow,
                        const float* __restrict__ u, const float* __restrict__ v,
                        __half* __restrict__ xh, __half* __restrict__ bwh,
                        __half* __restrict__ vwh, __half* __restrict__ owh,
                        __half* __restrict__ wh)
{
    int i = blockIdx.x * 256 + threadIdx.x;
    if (blockIdx.x == 0 && threadIdx.x < 64) g_sync[threadIdx.x] = 0;
    if (i >= NTOT) return;
    if (i >= NCVT) {
        // build_w: wh[h][n][r] = u/v transposed factor weights
        int idx = i - NCVT;
        int r = idx & 255;
        int n = (idx >> 8) & 127;
        int h = idx >> 15;
        float val = (n < 64)
            ? u[((size_t)h * Rdim + r) * Sdim + n]
            : v[((size_t)h * Rdim + r) * Sdim + (n - 64)];
        wh[idx] = __float2half_rn(val);
        return;
    }
    const float* src; __half* dst; int j;
    if (i < NX4)                  { src = x;  dst = xh;  j = i; }
    else if (i < NX4 + NB4)       { src = bw; dst = bwh; j = i - NX4; }
    else if (i < NX4 + NB4 + NV4) { src = vw; dst = vwh; j = i - NX4 - NB4; }
    else                          { src = ow; dst = owh; j = i - NX4 - NB4 - NV4; }
    float4 vv = ((const float4*)src)[j];
    ((__half2*)dst)[2 * j]     = __floats2half2_rn(vv.x, vv.y);
    ((__half2*)dst)[2 * j + 1] = __floats2half2_rn(vv.z, vv.w);
}

// ---------------------------------------------------------------------------
// fp16 mma.sync NT GEMM body (round-13/14 config)
// ---------------------------------------------------------------------------
#define HP 72   // smem pitch in halfs
template <int LAYOUT, bool HAS_BIAS, int OUT>
__device__ __forceinline__ void gemm_body(
    const __half* __restrict__ A, const __half* __restrict__ Bw,
    const float* __restrict__ bias, void* __restrict__ Cv,
    void* __restrict__ C2v, int Ndim_, int Kdim_, int bm, int bn, int head)
{
    extern __shared__ __half smh[];
    __half* As = smh;                   // [3][128][72]
    __half* Bs = smh + 3 * 128 * HP;    // [3][128][72]

    const int tid = threadIdx.x;
    const int lane = tid & 31;
    const int warp = tid >> 5;
    const int wy = warp & 1;
    const int wx = warp >> 1;

    if (LAYOUT == 2) Bw += (size_t)head * (128 * 256);

    const int sr = tid >> 3;
    const int sc8 = (tid & 7) * 8;

    const __half* Abase = A + (size_t)bm * Kdim_;
    const __half* Bbase = Bw + (size_t)bn * Kdim_;

    float acc[4][4][4];
#pragma unroll
    for (int i = 0; i < 4; i++)
#pragma unroll
        for (int j = 0; j < 4; j++)
#pragma unroll
            for (int e = 0; e < 4; e++) acc[i][j][e] = 0.f;

    const int nch = Kdim_ >> 6;

    auto load_chunk = [&](int ch, int buf) {
        const __half* An = Abase + ch * 64;
        const __half* Bn = Bbase + ch * 64;
        __half* Ad = As + buf * 128 * HP;
        __half* Bd = Bs + buf * 128 * HP;
#pragma unroll
        for (int i = 0; i < 4; i++) {
            int r = sr + i * 32;
            cp16(Ad + r * HP + sc8, An + (size_t)r * Kdim_ + sc8);
            cp16(Bd + r * HP + sc8, Bn + (size_t)r * Kdim_ + sc8);
        }
        CP_COMMIT();
    };

    load_chunk(0, 0);
    if (nch > 1) load_chunk(1, 1);

    const int quad = lane >> 3;
    const int r8 = lane & 7;
    const int a_off = ((quad & 1) * 8 + r8) * HP + (quad >> 1) * 8;
    const int b_off = ((quad >> 1) * 8 + r8) * HP + (quad & 1) * 8;

    const uint32_t smem_s = (uint32_t)__cvta_generic_to_shared(smh);
    const uint32_t asl = smem_s + (wy * 64 * HP + a_off) * 2;
    const uint32_t bsl = smem_s + (3 * 128 * HP + wx * 32 * HP + b_off) * 2;

    int buf = 0;
    for (int ch = 0; ch < nch; ch++) {
        if (ch + 1 < nch) { CP_WAIT1(); } else { CP_WAIT0(); }
        __syncthreads();

        if (ch + 2 < nch) {
            int nb = buf + 2; if (nb >= 3) nb -= 3;
            load_chunk(ch + 2, nb);
        }

        const uint32_t ab = asl + (buf * 128 * HP) * 2;
        const uint32_t bb = bsl + (buf * 128 * HP) * 2;
#pragma unroll
        for (int ks = 0; ks < 4; ks++) {
            const int kk2 = ks * 16 * 2;
            uint32_t af[4][4];
#pragma unroll
            for (int mf = 0; mf < 4; mf++)
                ldmatrix_x4(af[mf][0], af[mf][1], af[mf][2], af[mf][3],
                            ab + (mf * 16 * HP) * 2 + kk2);
            uint32_t bf[4][2];
#pragma unroll
            for (int p = 0; p < 2; p++)
                ldmatrix_x4(bf[2 * p][0], bf[2 * p][1], bf[2 * p + 1][0], bf[2 * p + 1][1],
                            bb + (p * 16 * HP) * 2 + kk2);
#pragma unroll
            for (int mf = 0; mf < 4; mf++)
#pragma unroll
                for (int nf = 0; nf < 4; nf++)
                    mma_f16(acc[mf][nf][0], acc[mf][nf][1], acc[mf][nf][2], acc[mf][nf][3],
                            af[mf][0], af[mf][1], af[mf][2], af[mf][3],
                            bf[nf][0], bf[nf][1]);
        }
        if (++buf == 3) buf = 0;
    }

    const int g = lane >> 2;
    const int tg = lane & 3;
#pragma unroll
    for (int mf = 0; mf < 4; mf++) {
#pragma unroll
        for (int nf = 0; nf < 4; nf++) {
            const int m0 = bm + wy * 64 + mf * 16 + g;
            const int n0 = bn + wx * 32 + nf * 8 + tg * 2;
            float v0 = acc[mf][nf][0], v1 = acc[mf][nf][1];
            float v2 = acc[mf][nf][2], v3 = acc[mf][nf][3];
            if (HAS_BIAS) {
                float b0 = bias[n0], b1 = bias[n0 + 1];
                v0 += b0; v1 += b1; v2 += b0; v3 += b1;
            }
            if (LAYOUT == 2 && n0 < 64) {
                v0 *= ATTN_SCALE; v1 *= ATTN_SCALE; v2 *= ATTN_SCALE; v3 *= ATTN_SCALE;
            }

            if (OUT == 2) {
                __half2 lo = __floats2half2_rn(v0, v1);
                __half2 hi = __floats2half2_rn(v2, v3);
                if (LAYOUT == 0) {
                    __half* C = (__half*)Cv;
                    *(__half2*)(C + (size_t)m0 * Ndim_ + n0) = lo;
                    *(__half2*)(C + (size_t)(m0 + 8) * Ndim_ + n0) = hi;
                } else if (LAYOUT == 1) {
                    __half* C = (__half*)Cv;
                    const int h = n0 >> 6, d = n0 & 63;
                    const int b_ = m0 >> 11, t = m0 & 2047;
                    __half* dst = C + (((size_t)b_ * Hdim + h) * Tdim + t) * Ddim + d;
                    *(__half2*)dst = lo;
                    *(__half2*)(dst + 8 * Ddim) = hi;
                } else {
                    __half* base = (n0 < 64) ? (__half*)Cv : (__half*)C2v;
                    const int s0 = n0 & 63;
                    const int b_ = m0 >> 11, t = m0 & 2047;
                    __half* dst = base + (((size_t)b_ * Hdim + head) * Tdim + t) * Sdim + s0;
                    *(__half2*)dst = lo;
                    *(__half2*)(dst + 8 * Sdim) = hi;
                }
            } else {
                float* C = (float*)Cv;
                *(float2*)(C + (size_t)m0 * Ndim_ + n0) = make_float2(v0, v1);
                *(float2*)(C + (size_t)(m0 + 8) * Ndim_ + n0) = make_float2(v2, v3);
            }
        }
    }
}

template <int LAYOUT, bool HAS_BIAS, int OUT>
__global__ void __launch_bounds__(256, 2)
gemm_h(const __half* __restrict__ A, const __half* __restrict__ Bw,
       const float* __restrict__ bias, void* __restrict__ Cv,
       void* __restrict__ C2v, int Ndim_, int Kdim_)
{
    gemm_body<LAYOUT, HAS_BIAS, OUT>(A, Bw, bias, Cv, C2v, Ndim_, Kdim_,
                                     blockIdx.y * 128, blockIdx.x * 128, blockIdx.z);
}

// Merged latent + v-proj kernel: flat grid of 128 (latent) + 512 (v) CTAs.
__global__ void __launch_bounds__(256, 2)
gemm_lv(const __half* __restrict__ xh, const __half* __restrict__ bwh,
        const __half* __restrict__ vwh, const float* __restrict__ vb,
        __half* __restrict__ lat, __half* __restrict__ vh)
{
    const int c = blockIdx.x;
    if (c < 128) {
        gemm_body<0, false, 2>(xh, bwh, nullptr, lat, nullptr, Rdim, Cdim,
                               (c >> 1) * 128, (c & 1) * 128, 0);
    } else {
        const int c2 = c - 128;
        gemm_body<1, true, 2>(xh, vwh, vb, vh, nullptr, Cdim, Cdim,
                              (c2 >> 3) * 128, (c2 & 7) * 128, 0);
    }
}

// ---------------------------------------------------------------------------
// Flash attention body (round-14 best config: Q tile 128, Q-frags hoisted,
// 3-stage cp.async K/V, one barrier per tile). Signals g_sync on completion.
// ---------------------------------------------------------------------------
__device__ __forceinline__ void flash_body(
    const __half* __restrict__ q, const __half* __restrict__ k,
    const __half* __restrict__ v, __half* __restrict__ y,
    int bh, int qb)
{
    extern __shared__ __half fsh[];
    __half* Qs = fsh;                  // [128][72] (staging only)
    __half* Ks = Qs + 128 * HP;        // [3][64][72]
    __half* Vs = Ks + 3 * 64 * HP;     // [3][64][72] natural [u][d]

    const int b = bh >> 4, h = bh & 15;
    const int q0 = qb * 128;
    const __half* Q = q + (size_t)bh * Tdim * Sdim;
    const __half* K = k + (size_t)bh * Tdim * Sdim;
    const __half* V = v + (size_t)bh * Tdim * Ddim;

    const int tid = threadIdx.x;
    const int lane = tid & 31;
    const int warp = tid >> 5;
    const int wrow = warp * 16;
    const int g = lane >> 2;
    const int tg = lane & 3;

    const int nkt = (q0 + 128) >> 6;   // >= 2

    auto load_kv = [&](int kt, int st) {
        const int k0 = kt * 64;
        __half* Kd = Ks + st * 64 * HP;
        __half* Vd = Vs + st * 64 * HP;
#pragma unroll
        for (int i = 0; i < 2; i++) {
            int f = tid + i * 256;
            int u = f >> 3, c8 = (f & 7) * 8;
            cp16(Kd + u * HP + c8, K + (size_t)(k0 + u) * Sdim + c8);
            cp16(Vd + u * HP + c8, V + (size_t)(k0 + u) * Ddim + c8);
        }
        CP_COMMIT();
    };

    load_kv(0, 0);
    load_kv(1, 1);

#pragma unroll
    for (int i = 0; i < 4; i++) {
        int f = tid + i * 256;
        int r = f >> 3, c8 = (f & 7) * 8;
        *(uint4*)&Qs[r * HP + c8] = *(const uint4*)&Q[(size_t)(q0 + r) * Sdim + c8];
    }

    const unsigned FULL = 0xffffffffu;
    const int quad = lane >> 3;
    const int r8 = lane & 7;
    const int a_off = ((quad & 1) * 8 + r8) * HP + (quad >> 1) * 8;
    const int b_off = ((quad >> 1) * 8 + r8) * HP + (quad & 1) * 8;
    const int lm_row = ((lane >> 3) & 1) * 8 + (lane & 7);
    const int lm_dfo = lane >> 4;

    const uint32_t fsh_s = (uint32_t)__cvta_generic_to_shared(fsh);
    const uint32_t qa_s = fsh_s + (wrow * HP + a_off) * 2;
    const uint32_t ks_s = fsh_s + (128 * HP + b_off) * 2;

    __syncthreads();
    uint32_t qf[4][4];
#pragma unroll
    for (int ks = 0; ks < 4; ks++)
        ldmatrix_x4(qf[ks][0], qf[ks][1], qf[ks][2], qf[ks][3], qa_s + ks * 16 * 2);

    float o[8][4];
#pragma unroll
    for (int df = 0; df < 8; df++)
#pragma unroll
        for (int e = 0; e < 4; e++) o[df][e] = 0.f;
    float m0 = -1e30f, m1 = -1e30f, l0 = 0.f, l1 = 0.f;

    int st = 0;
    for (int kt = 0; kt < nkt; kt++) {
        if (kt + 1 < nkt) { CP_WAIT1(); } else { CP_WAIT0(); }
        __syncthreads();

        if (kt + 2 < nkt) {
            int ns = st + 2; if (ns >= 3) ns -= 3;
            load_kv(kt + 2, ns);
        }

        const __half* Vb = Vs + st * 64 * HP;
        const uint32_t kb = ks_s + (st * 64 * HP) * 2;
        const int k0 = kt * 64;

        float sacc[8][4];
#pragma unroll
        for (int jf = 0; jf < 8; jf++)
#pragma unroll
            for (int e = 0; e < 4; e++) sacc[jf][e] = 0.f;
#pragma unroll
        for (int ks = 0; ks < 4; ks++) {
            const int kk2 = ks * 16 * 2;
            uint32_t bf[8][2];
#pragma unroll
            for (int p = 0; p < 4; p++)
                ldmatrix_x4(bf[2 * p][0], bf[2 * p][1], bf[2 * p + 1][0], bf[2 * p + 1][1],
                            kb + (p * 16 * HP) * 2 + kk2);
#pragma unroll
            for (int jf = 0; jf < 8; jf++)
                mma_f16(sacc[jf][0], sacc[jf][1], sacc[jf][2], sacc[jf][3],
                        qf[ks][0], qf[ks][1], qf[ks][2], qf[ks][3],
                        bf[jf][0], bf[jf][1]);
        }

        const int r0 = q0 + wrow + g;
        const int r1 = r0 + 8;
        if (k0 + 63 > q0 + wrow) {
#pragma unroll
            for (int jf = 0; jf < 8; jf++) {
                const int c0 = k0 + jf * 8 + 2 * tg;
                if (c0 > r0) sacc[jf][0] = -1e30f;
                if (c0 + 1 > r0) sacc[jf][1] = -1e30f;
                if (c0 > r1) sacc[jf][2] = -1e30f;
                if (c0 + 1 > r1) sacc[jf][3] = -1e30f;
            }
        }

        float mx0 = -1e30f, mx1 = -1e30f;
#pragma unroll
        for (int jf = 0; jf < 8; jf++) {
            mx0 = fmaxf(mx0, fmaxf(sacc[jf][0], sacc[jf][1]));
            mx1 = fmaxf(mx1, fmaxf(sacc[jf][2], sacc[jf][3]));
        }
        mx0 = fmaxf(mx0, __shfl_xor_sync(FULL, mx0, 1));
        mx0 = fmaxf(mx0, __shfl_xor_sync(FULL, mx0, 2));
        mx1 = fmaxf(mx1, __shfl_xor_sync(FULL, mx1, 1));
        mx1 = fmaxf(mx1, __shfl_xor_sync(FULL, mx1, 2));

        float mn0 = fmaxf(m0, mx0), mn1 = fmaxf(m1, mx1);
        float al0 = fexp(m0 - mn0), al1 = fexp(m1 - mn1);
        m0 = mn0; m1 = mn1;

        float rs0 = 0.f, rs1 = 0.f;
#pragma unroll
        for (int jf = 0; jf < 8; jf++) {
            sacc[jf][0] = fexp(sacc[jf][0] - mn0);
            sacc[jf][1] = fexp(sacc[jf][1] - mn0);
            sacc[jf][2] = fexp(sacc[jf][2] - mn1);
            sacc[jf][3] = fexp(sacc[jf][3] - mn1);
            rs0 += sacc[jf][0] + sacc[jf][1];
            rs1 += sacc[jf][2] + sacc[jf][3];
        }
        rs0 += __shfl_xor_sync(FULL, rs0, 1);
        rs0 += __shfl_xor_sync(FULL, rs0, 2);
        rs1 += __shfl_xor_sync(FULL, rs1, 1);
        rs1 += __shfl_xor_sync(FULL, rs1, 2);
        l0 = l0 * al0 + rs0;
        l1 = l1 * al1 + rs1;

#pragma unroll
        for (int df = 0; df < 8; df++) {
            o[df][0] *= al0; o[df][1] *= al0;
            o[df][2] *= al1; o[df][3] *= al1;
        }

        const uint32_t vb_s = (uint32_t)__cvta_generic_to_shared(Vb);
#pragma unroll
        for (int ks2 = 0; ks2 < 4; ks2++) {
            uint32_t a0 = packh2(sacc[2 * ks2][0],     sacc[2 * ks2][1]);
            uint32_t a1 = packh2(sacc[2 * ks2][2],     sacc[2 * ks2][3]);
            uint32_t a2 = packh2(sacc[2 * ks2 + 1][0], sacc[2 * ks2 + 1][1]);
            uint32_t a3 = packh2(sacc[2 * ks2 + 1][2], sacc[2 * ks2 + 1][3]);
            const uint32_t rowaddr = vb_s + ((16 * ks2 + lm_row) * HP) * 2;
#pragma unroll
            for (int df2 = 0; df2 < 4; df2++) {
                uint32_t b0, b1, b2, b3;
                ldmatrix_x4_trans(b0, b1, b2, b3,
                                  rowaddr + (16 * df2 + 8 * lm_dfo) * 2);
                mma_f16(o[2 * df2][0], o[2 * df2][1], o[2 * df2][2], o[2 * df2][3],
                        a0, a1, a2, a3, b0, b1);
                mma_f16(o[2 * df2 + 1][0], o[2 * df2 + 1][1], o[2 * df2 + 1][2], o[2 * df2 + 1][3],
                        a0, a1, a2, a3, b2, b3);
            }
        }
        if (++st == 3) st = 0;
    }

    // epilogue: y[b, t, h*64 + d] as fp16, then signal completion
    const float inv0 = 1.f / l0, inv1 = 1.f / l1;
    const int r0 = q0 + wrow + g;
    __half* y0 = y + ((size_t)b * Tdim + r0) * Cdim + h * 64;
    __half* y1 = y + ((size_t)b * Tdim + r0 + 8) * Cdim + h * 64;
#pragma unroll
    for (int df = 0; df < 8; df++) {
        const int d0 = df * 8 + 2 * tg;
        *(__half2*)(y0 + d0) = __floats2half2_rn(o[df][0] * inv0, o[df][1] * inv0);
        *(__half2*)(y1 + d0) = __floats2half2_rn(o[df][2] * inv1, o[df][3] * inv1);
    }

    __threadfence();       // each thread orders its y stores before the signal
    __syncthreads();
    if (tid == 0) atomicAdd(&g_sync[b * 16 + qb], 1);
}

// ---------------------------------------------------------------------------
// Merged flash + o-proj kernel.
// Bids [0,1024): flash (16 q-tiles x 64 bh, heaviest q-tiles first).
// Bids [1024,1536): o-proj row-block CTAs; each spins on its 16 producer
// signals then runs the normal GEMM body. Overlaps o-proj with flash tail.
// ---------------------------------------------------------------------------
__global__ void __launch_bounds__(256, 2)
flash_op(const __half* __restrict__ q, const __half* __restrict__ k,
         const __half* __restrict__ v, __half* __restrict__ y,
         const __half* __restrict__ ow, const float* __restrict__ ob,
         float* __restrict__ out)
{
    const int bx = blockIdx.x;
    if (bx < 1024) {
        const int bh = bx & 63;
        const int qb = 15 - (bx >> 6);     // heaviest q-tiles first
        flash_body(q, k, v, y, bh, qb);
    } else {
        const int c = bx - 1024;           // 0..511
        const int mbg = c >> 3;            // 0..63
        const int b_ = mbg >> 4;
        const int rb = 15 - (mbg & 15);    // match producer completion order
        const int mb = b_ * 16 + rb;
        const int bm = mb * 128;
        const int bn = (c & 7) * 128;
        if (threadIdx.x == 0) {
            while (((volatile int*)g_sync)[mb] < 16) __nanosleep(64);
        }
        __syncthreads();
        __threadfence();
        gemm_body<0, true, 0>(y, ow, ob, out, nullptr, Cdim, Cdim, bm, bn, 0);
    }
}

// ---------------------------------------------------------------------------
extern "C" void kernel_launch(void* const* d_in, const int* in_sizes, int n_in,
                              void* d_out, int out_size)
{
    const float* x  = (const float*)d_in[0];
    const float* bw = (const float*)d_in[1];
    const float* uf = (const float*)d_in[2];
    const float* vf = (const float*)d_in[3];
    const float* vw = (const float*)d_in[4];
    const float* vb = (const float*)d_in[5];
    const float* ow = (const float*)d_in[6];
    const float* ob = (const float*)d_in[7];
    float* out = (float*)d_out;

    __half *qh, *kh, *vh, *xh, *bwh, *vwh, *owh, *wh, *lath, *yh;
    cudaGetSymbolAddress((void**)&qh, g_qh);
    cudaGetSymbolAddress((void**)&kh, g_kh);
    cudaGetSymbolAddress((void**)&vh, g_vh);
    cudaGetSymbolAddress((void**)&xh, g_xh);
    cudaGetSymbolAddress((void**)&bwh, g_bwh);
    cudaGetSymbolAddress((void**)&vwh, g_vwh);
    cudaGetSymbolAddress((void**)&owh, g_owh);
    cudaGetSymbolAddress((void**)&wh, g_wh);
    cudaGetSymbolAddress((void**)&lath, g_lath);
    cudaGetSymbolAddress((void**)&yh, g_yh);

    const int GSMEM = 2 * 3 * 128 * HP * 2;             // 110592 bytes
    cudaFuncSetAttribute(gemm_lv,             cudaFuncAttributeMaxDynamicSharedMemorySize, GSMEM);
    cudaFuncSetAttribute(gemm_h<2, false, 2>, cudaFuncAttributeMaxDynamicSharedMemorySize, GSMEM);
    cudaFuncSetAttribute(flash_op,            cudaFuncAttributeMaxDynamicSharedMemorySize, GSMEM);

    // one-shot fp16 conversions + factor transpose + sync-counter reset
    cvt_all<<<(NTOT + 255) / 256, 256>>>(x, bw, vw, ow, uf, vf,
                                         xh, bwh, vwh, owh, wh);

    // latent (128 CTAs) merged with v-proj (512 CTAs)
    gemm_lv<<<640, 256, GSMEM>>>(xh, bwh, vwh, vb, lath, vh);

    // q,k per head (q pre-scaled) -> fp16 [B,H,T,64]
    gemm_h<2, false, 2><<<dim3(1, Mrows / 128, Hdim), 256, GSMEM>>>(
        lath, wh, nullptr, qh, kh, 128, Rdim);

    // flash attention (1024 CTAs) + o-proj (512 CTAs) merged with
    // fine-grained producer/consumer sync -> overlaps o-proj with flash tail
    flash_op<<<1536, 256, GSMEM>>>(qh, kh, vh, yh, owh, ob, out);
}